// round 5
// baseline (speedup 1.0000x reference)
#include <cuda_runtime.h>
#include <cuda_fp16.h>
#include <math_constants.h>
#include <cstdint>

// Problem constants: B=512, D=256, C=100000, m=4, lambda=1000
#define MAX_C 100000
#define MAX_B 512
#define DD    256

__device__ __half g_xh[(size_t)MAX_B * DD];   // fp16(normalized X)
__device__ float  g_xlen[MAX_B];

// ---------------------------------------------------------------------------
// Helpers
// ---------------------------------------------------------------------------
__device__ __forceinline__ uint32_t smem_u32(const void* p) {
    uint32_t a;
    asm("{ .reg .u64 t; cvta.to.shared.u64 t, %1; cvt.u32.u64 %0, t; }" : "=r"(a) : "l"(p));
    return a;
}
__device__ __forceinline__ void cp_async16(uint32_t dst, const void* src) {
    asm volatile("cp.async.cg.shared.global [%0], [%1], 16;" :: "r"(dst), "l"(src));
}
__device__ __forceinline__ void cp_commit() {
    asm volatile("cp.async.commit_group;" ::: "memory");
}
template <int N> __device__ __forceinline__ void cp_wait() {
    asm volatile("cp.async.wait_group %0;" :: "n"(N) : "memory");
}
__device__ __forceinline__ void ldsm_x4(uint32_t& r0, uint32_t& r1, uint32_t& r2, uint32_t& r3,
                                        uint32_t addr) {
    asm volatile("ldmatrix.sync.aligned.m8n8.x4.shared.b16 {%0,%1,%2,%3}, [%4];"
                 : "=r"(r0), "=r"(r1), "=r"(r2), "=r"(r3) : "r"(addr));
}
__device__ __forceinline__ void mma_16816(float& c0, float& c1, float& c2, float& c3,
                                          uint32_t a0, uint32_t a1, uint32_t a2, uint32_t a3,
                                          uint32_t b0, uint32_t b1) {
    asm volatile("mma.sync.aligned.m16n8k16.row.col.f32.f16.f16.f32 "
                 "{%0,%1,%2,%3}, {%4,%5,%6,%7}, {%8,%9}, {%0,%1,%2,%3};"
                 : "+f"(c0), "+f"(c1), "+f"(c2), "+f"(c3)
                 : "r"(a0), "r"(a1), "r"(a2), "r"(a3), "r"(b0), "r"(b1));
}

// ---------------------------------------------------------------------------
// X prep: normalize rows -> fp16. One warp per row, D = 256. (~2us)
// ---------------------------------------------------------------------------
__global__ void xprep_kernel(const float* __restrict__ X, int B) {
    int row  = (blockIdx.x * blockDim.x + threadIdx.x) >> 5;
    int lane = threadIdx.x & 31;
    if (row >= B) return;
    const float* p = X + (size_t)row * DD;
    float4 v0 = *(const float4*)(p + lane * 4);
    float4 v1 = *(const float4*)(p + 128 + lane * 4);
    float s = v0.x*v0.x + v0.y*v0.y + v0.z*v0.z + v0.w*v0.w
            + v1.x*v1.x + v1.y*v1.y + v1.z*v1.z + v1.w*v1.w;
    #pragma unroll
    for (int o = 16; o; o >>= 1) s += __shfl_xor_sync(0xffffffffu, s, o);
    float len = sqrtf(s);
    float inv = 1.0f / len;
    if (lane == 0) g_xlen[row] = len;
    __half2 h0 = __floats2half2_rn(v0.x * inv, v0.y * inv);
    __half2 h1 = __floats2half2_rn(v0.z * inv, v0.w * inv);
    __half2 h2 = __floats2half2_rn(v1.x * inv, v1.y * inv);
    __half2 h3 = __floats2half2_rn(v1.z * inv, v1.w * inv);
    size_t base = (size_t)row * DD;
    *(__half2*)(g_xh + base + lane * 4)           = h0;
    *(__half2*)(g_xh + base + lane * 4 + 2)       = h1;
    *(__half2*)(g_xh + base + 128 + lane * 4)     = h2;
    *(__half2*)(g_xh + base + 128 + lane * 4 + 2) = h3;
}

// ---------------------------------------------------------------------------
// Fused GEMM: CTA 128x256, BK=64, 8 warps (2m x 4n), warp tile 64x64.
// Raw fp32 W staged via cp.async; cvt(c+1) overlapped with MMA(c).
// ---------------------------------------------------------------------------
#define BM 128
#define BN 256
#define BK 64
#define NCHUNK (DD / BK)                       // 4

// smem layout
#define STG_OFF   0                            // 64 KB fp32 W staging (single)
#define BH_OFF    65536                        // 2 x 32 KB fp16 B
#define A_OFF     131072                       // 3 x 16 KB fp16 A
#define WLEN_OFF  180224                       // 1 KB wlen_inv[256]
#define SMEM_TOTAL 181248

// smem xor swizzle for 128-byte fp16 rows
__device__ __forceinline__ uint32_t sw_off(int row, int blk) {
    return (uint32_t)(row * 128 + ((blk ^ (row & 7)) * 16));
}

__global__ __launch_bounds__(256, 1)
void angle_mma_fused(const float* __restrict__ W, const int* __restrict__ Y,
                     float* __restrict__ out, int C)
{
    extern __shared__ char smem[];
    const uint32_t sbase = smem_u32(smem);
    const int tid  = threadIdx.x;
    const int wid  = tid >> 5;
    const int lane = tid & 31;
    const int wm   = wid >> 2;     // 0..1 : warp m (64 rows)
    const int wn   = wid & 3;      // 0..3 : warp n (64 cols)

    const int bm = blockIdx.x * BM;
    const int bn = blockIdx.y * BN;

    const uint32_t stg = sbase + STG_OFF;
    float* wlen_inv = (float*)(smem + WLEN_OFF);

    // ---- loaders ----
    auto load_a = [&](int stage, int kc) {
        const uint32_t ab = sbase + A_OFF + stage * 16384;
        #pragma unroll
        for (int i = 0; i < 4; i++) {
            int t2 = tid + i * 256;            // 0..1023
            int row = t2 >> 3, blk = t2 & 7;
            cp_async16(ab + sw_off(row, blk),
                       g_xh + (size_t)(bm + row) * DD + kc + blk * 8);
        }
    };
    auto load_bstg = [&](int kc) {
        #pragma unroll
        for (int i = 0; i < 16; i++) {
            int g = tid + i * 256;             // 0..4095
            int row = g >> 4, seg = g & 15;
            int rg = bn + row; if (rg >= C) rg = C - 1;
            cp_async16(stg + (uint32_t)g * 16, W + (size_t)rg * DD + kc + seg * 4);
        }
    };

    float sumsq[16];
    #pragma unroll
    for (int i = 0; i < 16; i++) sumsq[i] = 0.f;

    const uint32_t cvt_seg  = (uint32_t)(tid & 15);
    const uint32_t cvt_blkb = cvt_seg >> 1;
    const uint32_t cvt_sub  = (cvt_seg & 1) * 8;

    // cvt: fp32 staging -> fp16 Bh[buf] (+ sumsq)
    auto do_cvt = [&](int buf) {
        const uint32_t bh = sbase + BH_OFF + (uint32_t)buf * 32768;
        #pragma unroll
        for (int i = 0; i < 16; i++) {
            int g = tid + i * 256;
            float4 v = *(const float4*)(smem + STG_OFF + (size_t)g * 16);
            sumsq[i] += v.x*v.x + v.y*v.y + v.z*v.z + v.w*v.w;
            __half2 h0 = __floats2half2_rn(v.x, v.y);
            __half2 h1 = __floats2half2_rn(v.z, v.w);
            int row = g >> 4;
            uint32_t off = (uint32_t)row * 128 +
                           ((cvt_blkb ^ (uint32_t)(row & 7)) * 16) + cvt_sub;
            *(uint2*)((char*)smem + BH_OFF + buf * 32768 + off) =
                make_uint2(*(uint32_t*)&h0, *(uint32_t*)&h1);
        }
        (void)bh;
    };

    // ---- prologue ----
    load_bstg(0); load_a(0, 0); cp_commit();
    cp_wait<0>();
    __syncthreads();
    do_cvt(0);                                  // Bh[0] <- chunk 0
    load_bstg(BK); load_a(1, BK); cp_commit();  // stg <- chunk 1 (safe: own reads done)

    float c[4][8][4];
    #pragma unroll
    for (int mt = 0; mt < 4; mt++)
        #pragma unroll
        for (int nt = 0; nt < 8; nt++)
            #pragma unroll
            for (int q = 0; q < 4; q++) c[mt][nt][q] = 0.f;

    const int a_hi = lane >> 4;
    int a_row[4], b_row[4];
    #pragma unroll
    for (int mt = 0; mt < 4; mt++) a_row[mt] = wm * 64 + mt * 16 + (lane & 15);
    #pragma unroll
    for (int bt = 0; bt < 4; bt++) b_row[bt] = wn * 64 + bt * 16 + ((lane >> 3) & 1) * 8 + (lane & 7);

    // ---- main loop ----
    #pragma unroll
    for (int ck = 0; ck < NCHUNK; ck++) {
        cp_wait<0>();               // stg(ck+1) + A(ck+1) landed (last iter: nothing)
        __syncthreads();            // Bh[ck&1] visible; prev readers done

        if (ck + 1 < NCHUNK) do_cvt((ck + 1) & 1);
        if (ck + 2 < NCHUNK) {      // stg refill after own cvt reads; A -> 3rd buffer
            load_bstg((ck + 2) * BK);
            load_a((ck + 2) % 3, (ck + 2) * BK);
            cp_commit();
        }

        // MMA(ck): A[ck%3], Bh[ck&1]
        const uint32_t ab = sbase + A_OFF + (uint32_t)(ck % 3) * 16384;
        const uint32_t bh = sbase + BH_OFF + (uint32_t)(ck & 1) * 32768;
        #pragma unroll
        for (int ks = 0; ks < 4; ks++) {
            uint32_t a[4][4], b[4][4];
            #pragma unroll
            for (int mt = 0; mt < 4; mt++)
                ldsm_x4(a[mt][0], a[mt][1], a[mt][2], a[mt][3],
                        ab + sw_off(a_row[mt], ks * 2 + a_hi));
            #pragma unroll
            for (int bt = 0; bt < 4; bt++)
                ldsm_x4(b[bt][0], b[bt][1], b[bt][2], b[bt][3],
                        bh + sw_off(b_row[bt], ks * 2 + a_hi));
            #pragma unroll
            for (int mt = 0; mt < 4; mt++) {
                #pragma unroll
                for (int nt = 0; nt < 8; nt++) {
                    const int bt = nt >> 1, sub = nt & 1;
                    mma_16816(c[mt][nt][0], c[mt][nt][1], c[mt][nt][2], c[mt][nt][3],
                              a[mt][0], a[mt][1], a[mt][2], a[mt][3],
                              b[bt][sub], b[bt][2 + sub]);
                }
            }
        }
    }

    // ---- reduce sumsq -> wlen_inv[256] (16-lane groups own one row each) ----
    #pragma unroll
    for (int i = 0; i < 16; i++) {
        float s = sumsq[i];
        s += __shfl_xor_sync(0xffffffffu, s, 1);
        s += __shfl_xor_sync(0xffffffffu, s, 2);
        s += __shfl_xor_sync(0xffffffffu, s, 4);
        s += __shfl_xor_sync(0xffffffffu, s, 8);
        if ((tid & 15) == 0) wlen_inv[(tid >> 4) + i * 16] = rsqrtf(s);
    }
    __syncthreads();

    // ---- epilogue: cos -> feat (+ margin at label) ----
    const float inv_pi     = 1.0f / CUDART_PI_F;
    const float inv_1plamb = 1.0f / 1001.0f;

    #pragma unroll
    for (int mt = 0; mt < 4; mt++) {
        const int r0 = bm + wm * 64 + mt * 16 + (lane >> 2);
        const int r1 = r0 + 8;
        const float xl0 = g_xlen[r0], xl1 = g_xlen[r1];
        const int  lab0 = Y[r0],      lab1 = Y[r1];
        #pragma unroll
        for (int nt = 0; nt < 8; nt++) {
            const int lc  = wn * 64 + nt * 8 + (lane & 3) * 2;
            const int col = bn + lc;
            if (col >= C) continue;          // col even, C even -> col+1 valid
            const float wli0 = wlen_inv[lc];
            const float wli1 = wlen_inv[lc + 1];
            #pragma unroll
            for (int half = 0; half < 2; half++) {
                const int   rr  = half ? r1 : r0;
                const float xl  = half ? xl1 : xl0;
                const int   lab = half ? lab1 : lab0;
                float v0 = c[mt][nt][half * 2 + 0] * wli0;
                float v1 = c[mt][nt][half * 2 + 1] * wli1;
                v0 = fminf(fmaxf(v0, -1.0f), 1.0f);
                v1 = fminf(fmaxf(v1, -1.0f), 1.0f);
                float f0 = v0 * xl, f1 = v1 * xl;
                if (col == lab || col + 1 == lab) {
                    const bool second = (col + 1 == lab);
                    float cv = second ? v1 : v0;
                    float c2   = cv * cv;
                    float cosm = 8.0f * c2 * c2 - 8.0f * c2 + 1.0f;
                    float kf   = floorf(4.0f * acosf(cv) * inv_pi);
                    float sign = 1.0f - 2.0f * fmodf(kf, 2.0f);
                    float phi  = sign * cosm - 2.0f * kf;
                    float fm   = second ? f1 : f0;
                    fm += (phi * xl - fm) * inv_1plamb;
                    if (second) f1 = fm; else f0 = fm;
                }
                *(float2*)(out + (size_t)rr * C + col) = make_float2(f0, f1);
            }
        }
    }
}

// ---------------------------------------------------------------------------
// Launch
// ---------------------------------------------------------------------------
extern "C" void kernel_launch(void* const* d_in, const int* in_sizes, int n_in,
                              void* d_out, int out_size)
{
    const float* x = (const float*)d_in[0];
    const float* w = (const float*)d_in[1];
    const int*   y = (const int*)d_in[2];
    float* out     = (float*)d_out;

    const int B = in_sizes[2];            // 512
    const int D = in_sizes[0] / B;        // 256
    const int C = in_sizes[1] / D;        // 100000
    (void)D;

    static bool attr_set = false;
    if (!attr_set) {
        cudaFuncSetAttribute(angle_mma_fused,
                             cudaFuncAttributeMaxDynamicSharedMemorySize, SMEM_TOTAL);
        attr_set = true;
    }

    {
        int wpb = 8;
        xprep_kernel<<<(B + wpb - 1) / wpb, wpb * 32>>>(x, B);
    }

    // grid.x = m tiles (fastest -> adjacent CTAs share the same W n-stripe in L2)
    dim3 grid(B / BM, (C + BN - 1) / BN);
    angle_mma_fused<<<grid, 256, SMEM_TOTAL>>>(w, y, out, C);
}

// round 6
// speedup vs baseline: 1.6309x; 1.6309x over previous
#include <cuda_runtime.h>
#include <cuda_fp16.h>
#include <math_constants.h>
#include <cstdint>

// Problem constants: B=512, D=256, C=100000, m=4, lambda=1000
#define MAX_C 100000
#define MAX_B 512
#define DD    256

__device__ __half g_wh[(size_t)MAX_C * DD];   // fp16(normalized W)
__device__ __half g_xh[(size_t)MAX_B * DD];   // fp16(normalized X)
__device__ float  g_xlen[MAX_B];

// ---------------------------------------------------------------------------
// Helpers
// ---------------------------------------------------------------------------
__device__ __forceinline__ uint32_t smem_u32(const void* p) {
    uint32_t a;
    asm("{ .reg .u64 t; cvta.to.shared.u64 t, %1; cvt.u32.u64 %0, t; }" : "=r"(a) : "l"(p));
    return a;
}
__device__ __forceinline__ void cp_async16(uint32_t dst, const void* src) {
    asm volatile("cp.async.cg.shared.global [%0], [%1], 16;" :: "r"(dst), "l"(src));
}
__device__ __forceinline__ void cp_commit() {
    asm volatile("cp.async.commit_group;" ::: "memory");
}
template <int N> __device__ __forceinline__ void cp_wait() {
    asm volatile("cp.async.wait_group %0;" :: "n"(N) : "memory");
}
__device__ __forceinline__ void ldsm_x4(uint32_t& r0, uint32_t& r1, uint32_t& r2, uint32_t& r3,
                                        uint32_t addr) {
    asm volatile("ldmatrix.sync.aligned.m8n8.x4.shared.b16 {%0,%1,%2,%3}, [%4];"
                 : "=r"(r0), "=r"(r1), "=r"(r2), "=r"(r3) : "r"(addr));
}
__device__ __forceinline__ void mma_16816(float& c0, float& c1, float& c2, float& c3,
                                          uint32_t a0, uint32_t a1, uint32_t a2, uint32_t a3,
                                          uint32_t b0, uint32_t b1) {
    asm volatile("mma.sync.aligned.m16n8k16.row.col.f32.f16.f16.f32 "
                 "{%0,%1,%2,%3}, {%4,%5,%6,%7}, {%8,%9}, {%0,%1,%2,%3};"
                 : "+f"(c0), "+f"(c1), "+f"(c2), "+f"(c3)
                 : "r"(a0), "r"(a1), "r"(a2), "r"(a3), "r"(b0), "r"(b1));
}

// ---------------------------------------------------------------------------
// Prep kernels: normalize rows -> fp16. One warp per row, D = 256.
// ---------------------------------------------------------------------------
__global__ void wprep_kernel(const float* __restrict__ W, int C) {
    int row  = (blockIdx.x * blockDim.x + threadIdx.x) >> 5;
    int lane = threadIdx.x & 31;
    if (row >= C) return;
    const float* p = W + (size_t)row * DD;
    float4 v0 = *(const float4*)(p + lane * 4);
    float4 v1 = *(const float4*)(p + 128 + lane * 4);
    float s = v0.x*v0.x + v0.y*v0.y + v0.z*v0.z + v0.w*v0.w
            + v1.x*v1.x + v1.y*v1.y + v1.z*v1.z + v1.w*v1.w;
    #pragma unroll
    for (int o = 16; o; o >>= 1) s += __shfl_xor_sync(0xffffffffu, s, o);
    float inv = rsqrtf(s);
    __half2 h0 = __floats2half2_rn(v0.x * inv, v0.y * inv);
    __half2 h1 = __floats2half2_rn(v0.z * inv, v0.w * inv);
    __half2 h2 = __floats2half2_rn(v1.x * inv, v1.y * inv);
    __half2 h3 = __floats2half2_rn(v1.z * inv, v1.w * inv);
    size_t base = (size_t)row * DD;
    *(__half2*)(g_wh + base + lane * 4)           = h0;
    *(__half2*)(g_wh + base + lane * 4 + 2)       = h1;
    *(__half2*)(g_wh + base + 128 + lane * 4)     = h2;
    *(__half2*)(g_wh + base + 128 + lane * 4 + 2) = h3;
}

__global__ void xprep_kernel(const float* __restrict__ X, int B) {
    int row  = (blockIdx.x * blockDim.x + threadIdx.x) >> 5;
    int lane = threadIdx.x & 31;
    if (row >= B) return;
    const float* p = X + (size_t)row * DD;
    float4 v0 = *(const float4*)(p + lane * 4);
    float4 v1 = *(const float4*)(p + 128 + lane * 4);
    float s = v0.x*v0.x + v0.y*v0.y + v0.z*v0.z + v0.w*v0.w
            + v1.x*v1.x + v1.y*v1.y + v1.z*v1.z + v1.w*v1.w;
    #pragma unroll
    for (int o = 16; o; o >>= 1) s += __shfl_xor_sync(0xffffffffu, s, o);
    float len = sqrtf(s);
    float inv = 1.0f / len;
    if (lane == 0) g_xlen[row] = len;
    __half2 h0 = __floats2half2_rn(v0.x * inv, v0.y * inv);
    __half2 h1 = __floats2half2_rn(v0.z * inv, v0.w * inv);
    __half2 h2 = __floats2half2_rn(v1.x * inv, v1.y * inv);
    __half2 h3 = __floats2half2_rn(v1.z * inv, v1.w * inv);
    size_t base = (size_t)row * DD;
    *(__half2*)(g_xh + base + lane * 4)           = h0;
    *(__half2*)(g_xh + base + lane * 4 + 2)       = h1;
    *(__half2*)(g_xh + base + 128 + lane * 4)     = h2;
    *(__half2*)(g_xh + base + 128 + lane * 4 + 2) = h3;
}

// ---------------------------------------------------------------------------
// GEMM: CTA 128x256, 512 threads, 16 warps (2m x 8n), warp tile 64x32.
// A fully K-resident in smem; B triple-buffered over K chunks of 64.
// One barrier per chunk.
// ---------------------------------------------------------------------------
#define BM 128
#define BN 256
#define BK 64
#define NCHUNK (DD / BK)                 // 4

// smem: A 4 chunk-slabs of 16 KB; B 3 buffers of 32 KB
#define A_OFF      0                     // 65536
#define B_OFF      65536                 // + 3*32768 = 98304
#define SMEM_TOTAL 163840

// smem xor swizzle for 128-byte fp16 rows
__device__ __forceinline__ uint32_t sw_off(int row, int blk) {
    return (uint32_t)(row * 128 + ((blk ^ (row & 7)) * 16));
}

__global__ __launch_bounds__(512, 1)
void angle_mma_kernel(const int* __restrict__ Y, float* __restrict__ out, int C)
{
    extern __shared__ char smem[];
    const uint32_t sbase = smem_u32(smem);
    const int tid  = threadIdx.x;
    const int wid  = tid >> 5;
    const int lane = tid & 31;
    const int wm   = wid >> 3;     // 0..1 : warp m (64 rows)
    const int wn   = wid & 7;      // 0..7 : warp n (32 cols)

    const int bm = blockIdx.x * BM;
    const int bn = blockIdx.y * BN;

    // ---- loaders ----
    // A: all K resident, 4 slabs of [128 rows x 128B]
    auto load_a_all = [&]() {
        #pragma unroll
        for (int i = 0; i < 8; i++) {
            int t2 = tid + i * 512;               // 0..4095
            int chunk = t2 >> 10;
            int w3    = t2 & 1023;
            int row = w3 >> 3, blk = w3 & 7;
            cp_async16(sbase + A_OFF + chunk * 16384 + sw_off(row, blk),
                       g_xh + (size_t)(bm + row) * DD + chunk * BK + blk * 8);
        }
    };
    // B chunk: [256 rows x 128B] into buffer `buf`
    auto load_b = [&](int buf, int kc) {
        const uint32_t bb = sbase + B_OFF + (uint32_t)buf * 32768;
        #pragma unroll
        for (int i = 0; i < 4; i++) {
            int g = tid + i * 512;                // 0..2047
            int row = g >> 3, blk = g & 7;
            int rg = bn + row; if (rg >= C) rg = C - 1;
            cp_async16(bb + sw_off(row, blk),
                       g_wh + (size_t)rg * DD + kc + blk * 8);
        }
    };

    // ---- prologue: A + B0 (group0), B1 (group1) ----
    load_a_all();
    load_b(0, 0);
    cp_commit();
    load_b(1, BK);
    cp_commit();

    float c[4][4][4];
    #pragma unroll
    for (int mt = 0; mt < 4; mt++)
        #pragma unroll
        for (int nt = 0; nt < 4; nt++)
            #pragma unroll
            for (int q = 0; q < 4; q++) c[mt][nt][q] = 0.f;

    const int a_hi = lane >> 4;
    int a_row[4], b_row[2];
    #pragma unroll
    for (int mt = 0; mt < 4; mt++) a_row[mt] = wm * 64 + mt * 16 + (lane & 15);
    #pragma unroll
    for (int bt = 0; bt < 2; bt++) b_row[bt] = wn * 32 + bt * 16 + ((lane >> 3) & 1) * 8 + (lane & 7);

    // ---- main loop: one barrier per chunk ----
    #pragma unroll
    for (int ck = 0; ck < NCHUNK; ck++) {
        if (ck == NCHUNK - 1) cp_wait<0>(); else cp_wait<1>();
        __syncthreads();                          // B[ck] (+A on ck=0) visible

        if (ck + 2 < NCHUNK) {                    // refill into idle 3rd buffer
            load_b((ck + 2) % 3, (ck + 2) * BK);
            cp_commit();
        }

        const uint32_t ab = sbase + A_OFF + (uint32_t)ck * 16384;
        const uint32_t bb = sbase + B_OFF + (uint32_t)(ck % 3) * 32768;
        #pragma unroll
        for (int ks = 0; ks < 4; ks++) {
            uint32_t a[4][4], b[2][4];
            #pragma unroll
            for (int mt = 0; mt < 4; mt++)
                ldsm_x4(a[mt][0], a[mt][1], a[mt][2], a[mt][3],
                        ab + sw_off(a_row[mt], ks * 2 + a_hi));
            #pragma unroll
            for (int bt = 0; bt < 2; bt++)
                ldsm_x4(b[bt][0], b[bt][1], b[bt][2], b[bt][3],
                        bb + sw_off(b_row[bt], ks * 2 + a_hi));
            #pragma unroll
            for (int mt = 0; mt < 4; mt++) {
                #pragma unroll
                for (int nt = 0; nt < 4; nt++) {
                    const int bt = nt >> 1, sub = nt & 1;
                    mma_16816(c[mt][nt][0], c[mt][nt][1], c[mt][nt][2], c[mt][nt][3],
                              a[mt][0], a[mt][1], a[mt][2], a[mt][3],
                              b[bt][sub], b[bt][2 + sub]);
                }
            }
        }
    }

    // ---- epilogue: cos -> feat (+ margin at label) ----
    const float inv_pi     = 1.0f / CUDART_PI_F;
    const float inv_1plamb = 1.0f / 1001.0f;

    #pragma unroll
    for (int mt = 0; mt < 4; mt++) {
        const int r0 = bm + wm * 64 + mt * 16 + (lane >> 2);
        const int r1 = r0 + 8;
        const float xl0 = g_xlen[r0], xl1 = g_xlen[r1];
        const int  lab0 = Y[r0],      lab1 = Y[r1];
        #pragma unroll
        for (int nt = 0; nt < 4; nt++) {
            const int col = bn + wn * 32 + nt * 8 + (lane & 3) * 2;
            if (col >= C) continue;          // col even, C even -> col+1 valid
            #pragma unroll
            for (int half = 0; half < 2; half++) {
                const int   rr  = half ? r1 : r0;
                const float xl  = half ? xl1 : xl0;
                const int   lab = half ? lab1 : lab0;
                float v0 = c[mt][nt][half * 2 + 0];
                float v1 = c[mt][nt][half * 2 + 1];
                v0 = fminf(fmaxf(v0, -1.0f), 1.0f);
                v1 = fminf(fmaxf(v1, -1.0f), 1.0f);
                float f0 = v0 * xl, f1 = v1 * xl;
                if (col == lab || col + 1 == lab) {
                    const bool second = (col + 1 == lab);
                    float cv = second ? v1 : v0;
                    float c2   = cv * cv;
                    float cosm = 8.0f * c2 * c2 - 8.0f * c2 + 1.0f;
                    float kf   = floorf(4.0f * acosf(cv) * inv_pi);
                    float sign = 1.0f - 2.0f * fmodf(kf, 2.0f);
                    float phi  = sign * cosm - 2.0f * kf;
                    float fm   = second ? f1 : f0;
                    fm += (phi * xl - fm) * inv_1plamb;
                    if (second) f1 = fm; else f0 = fm;
                }
                *(float2*)(out + (size_t)rr * C + col) = make_float2(f0, f1);
            }
        }
    }
}

// ---------------------------------------------------------------------------
// Launch
// ---------------------------------------------------------------------------
extern "C" void kernel_launch(void* const* d_in, const int* in_sizes, int n_in,
                              void* d_out, int out_size)
{
    const float* x = (const float*)d_in[0];
    const float* w = (const float*)d_in[1];
    const int*   y = (const int*)d_in[2];
    float* out     = (float*)d_out;

    const int B = in_sizes[2];            // 512
    const int D = in_sizes[0] / B;        // 256
    const int C = in_sizes[1] / D;        // 100000
    (void)D;

    static bool attr_set = false;
    if (!attr_set) {
        cudaFuncSetAttribute(angle_mma_kernel,
                             cudaFuncAttributeMaxDynamicSharedMemorySize, SMEM_TOTAL);
        attr_set = true;
    }

    {
        int wpb = 8;
        wprep_kernel<<<(C + wpb - 1) / wpb, wpb * 32>>>(w, C);
        xprep_kernel<<<(B + wpb - 1) / wpb, wpb * 32>>>(x, B);
    }

    // grid.x = m tiles (fastest -> 4 CTAs share each W n-stripe in L2)
    dim3 grid(B / BM, (C + BN - 1) / BN);
    angle_mma_kernel<<<grid, 512, SMEM_TOTAL>>>(y, out, C);
}

// round 9
// speedup vs baseline: 1.8630x; 1.1423x over previous
#include <cuda_runtime.h>
#include <cuda_fp16.h>
#include <math_constants.h>
#include <cstdint>

// Problem constants: B=512, D=256, C=100000, m=4, lambda=1000
#define MAX_C 100000
#define MAX_B 512
#define DD    256

__device__ __half g_wh[(size_t)MAX_C * DD];   // fp16(normalized W)
__device__ __half g_xh[(size_t)MAX_B * DD];   // fp16(normalized X)
__device__ float  g_xlen[MAX_B];

// ---------------------------------------------------------------------------
// Helpers
// ---------------------------------------------------------------------------
__device__ __forceinline__ uint32_t smem_u32(const void* p) {
    uint32_t a;
    asm("{ .reg .u64 t; cvta.to.shared.u64 t, %1; cvt.u32.u64 %0, t; }" : "=r"(a) : "l"(p));
    return a;
}
__device__ __forceinline__ void cp_async16(uint32_t dst, const void* src) {
    asm volatile("cp.async.cg.shared.global [%0], [%1], 16;" :: "r"(dst), "l"(src));
}
__device__ __forceinline__ void cp_commit() {
    asm volatile("cp.async.commit_group;" ::: "memory");
}
template <int N> __device__ __forceinline__ void cp_wait() {
    asm volatile("cp.async.wait_group %0;" :: "n"(N) : "memory");
}
__device__ __forceinline__ void ldsm_x4(uint32_t& r0, uint32_t& r1, uint32_t& r2, uint32_t& r3,
                                        uint32_t addr) {
    asm volatile("ldmatrix.sync.aligned.m8n8.x4.shared.b16 {%0,%1,%2,%3}, [%4];"
                 : "=r"(r0), "=r"(r1), "=r"(r2), "=r"(r3) : "r"(addr));
}
__device__ __forceinline__ void mma_16816(float& c0, float& c1, float& c2, float& c3,
                                          uint32_t a0, uint32_t a1, uint32_t a2, uint32_t a3,
                                          uint32_t b0, uint32_t b1) {
    asm volatile("mma.sync.aligned.m16n8k16.row.col.f32.f16.f16.f32 "
                 "{%0,%1,%2,%3}, {%4,%5,%6,%7}, {%8,%9}, {%0,%1,%2,%3};"
                 : "+f"(c0), "+f"(c1), "+f"(c2), "+f"(c3)
                 : "r"(a0), "r"(a1), "r"(a2), "r"(a3), "r"(b0), "r"(b1));
}

// ---------------------------------------------------------------------------
// Merged prep: rows [0,C) -> normalize W row; rows [C,C+B) -> normalize X row.
// One warp per row, D = 256.
// ---------------------------------------------------------------------------
__global__ void prep_kernel(const float* __restrict__ W, const float* __restrict__ X,
                            int C, int B) {
    int row  = (blockIdx.x * blockDim.x + threadIdx.x) >> 5;
    int lane = threadIdx.x & 31;
    if (row >= C + B) return;
    const bool isx = row >= C;
    const int  r   = isx ? row - C : row;
    const float* src = (isx ? X : W) + (size_t)r * DD;
    __half*      dst = (isx ? g_xh : g_wh) + (size_t)r * DD;

    float4 v0 = *(const float4*)(src + lane * 4);
    float4 v1 = *(const float4*)(src + 128 + lane * 4);
    float s = v0.x*v0.x + v0.y*v0.y + v0.z*v0.z + v0.w*v0.w
            + v1.x*v1.x + v1.y*v1.y + v1.z*v1.z + v1.w*v1.w;
    #pragma unroll
    for (int o = 16; o; o >>= 1) s += __shfl_xor_sync(0xffffffffu, s, o);
    float inv = rsqrtf(s);
    if (isx && lane == 0) g_xlen[r] = s * inv;   // len = s / sqrt(s)
    __half2 h0 = __floats2half2_rn(v0.x * inv, v0.y * inv);
    __half2 h1 = __floats2half2_rn(v0.z * inv, v0.w * inv);
    __half2 h2 = __floats2half2_rn(v1.x * inv, v1.y * inv);
    __half2 h3 = __floats2half2_rn(v1.z * inv, v1.w * inv);
    *(__half2*)(dst + lane * 4)           = h0;
    *(__half2*)(dst + lane * 4 + 2)       = h1;
    *(__half2*)(dst + 128 + lane * 4)     = h2;
    *(__half2*)(dst + 128 + lane * 4 + 2) = h3;
}

// ---------------------------------------------------------------------------
// GEMM: CTA 128x128, 256 threads, 8 warps (2m x 4n), warp tile 64x32.
// A fully K-resident (loaded once); B 3-stage ring over K chunks of 64.
// Fragment double-buffering over ks.
// ---------------------------------------------------------------------------
#define BM 128
#define BN 128
#define BK 64
#define NCHUNK (DD / BK)                 // 4

// smem: A 4 chunk-slabs of 16 KB (65536); B ring 3 x 16 KB (49152)
#define A_OFF      0
#define B_OFF      65536
#define SMEM_TOTAL 114688                // 112 KB -> 2 CTAs/SM

// smem xor swizzle for 128-byte fp16 rows
__device__ __forceinline__ uint32_t sw_off(int row, int blk) {
    return (uint32_t)(row * 128 + ((blk ^ (row & 7)) * 16));
}

__global__ __launch_bounds__(256, 2)
void angle_mma_kernel(const int* __restrict__ Y, float* __restrict__ out, int C)
{
    extern __shared__ char smem[];
    const uint32_t sbase = smem_u32(smem);
    const int tid  = threadIdx.x;
    const int wid  = tid >> 5;
    const int lane = tid & 31;
    const int wm   = wid >> 2;     // 0..1 : warp m (64 rows)
    const int wn   = wid & 3;      // 0..3 : warp n (32 cols)

    const int bm = blockIdx.x * BM;
    const int bn = blockIdx.y * BN;

    // ---- loaders ----
    auto load_a_all = [&]() {       // 128 rows x 256 k, 4 slabs of 16 KB
        for (int i = 0; i < 16; i++) {
            int t2 = tid + i * 256;               // 0..4095
            int chunk = t2 >> 10;
            int w3    = t2 & 1023;
            int row = w3 >> 3, blk = w3 & 7;
            cp_async16(sbase + A_OFF + chunk * 16384 + sw_off(row, blk),
                       g_xh + (size_t)(bm + row) * DD + chunk * BK + blk * 8);
        }
    };
    auto load_b = [&](int buf, int kc) {          // 128 rows x 64 k
        const uint32_t bb = sbase + B_OFF + (uint32_t)buf * 16384;
        #pragma unroll
        for (int i = 0; i < 4; i++) {
            int g = tid + i * 256;                // 0..1023
            int row = g >> 3, blk = g & 7;
            int rg = bn + row; if (rg >= C) rg = C - 1;
            cp_async16(bb + sw_off(row, blk),
                       g_wh + (size_t)rg * DD + kc + blk * 8);
        }
    };

    // ---- prologue: group0 = A + B0, group1 = B1 ----
    load_a_all();
    load_b(0, 0);
    cp_commit();
    load_b(1, BK);
    cp_commit();

    float c[4][4][4];
    #pragma unroll
    for (int mt = 0; mt < 4; mt++)
        #pragma unroll
        for (int nt = 0; nt < 4; nt++)
            #pragma unroll
            for (int q = 0; q < 4; q++) c[mt][nt][q] = 0.f;

    const int a_hi = lane >> 4;
    int a_row[4], b_row[2];
    #pragma unroll
    for (int mt = 0; mt < 4; mt++) a_row[mt] = wm * 64 + mt * 16 + (lane & 15);
    #pragma unroll
    for (int bt = 0; bt < 2; bt++) b_row[bt] = wn * 32 + bt * 16 + ((lane >> 3) & 1) * 8 + (lane & 7);

    // ---- main loop: one barrier per chunk; ks-pipelined fragments ----
    #pragma unroll
    for (int ck = 0; ck < NCHUNK; ck++) {
        if (ck == NCHUNK - 1) cp_wait<0>(); else cp_wait<1>();
        __syncthreads();                          // B[ck] (+A on ck=0) visible

        if (ck + 2 < NCHUNK) {                    // refill idle 3rd buffer
            load_b((ck + 2) % 3, (ck + 2) * BK);
            cp_commit();
        }

        const uint32_t ab = sbase + A_OFF + (uint32_t)ck * 16384;
        const uint32_t bb = sbase + B_OFF + (uint32_t)(ck % 3) * 16384;

        uint32_t a[2][4][4], b[2][2][4];
        // preload ks = 0
        #pragma unroll
        for (int mt = 0; mt < 4; mt++)
            ldsm_x4(a[0][mt][0], a[0][mt][1], a[0][mt][2], a[0][mt][3],
                    ab + sw_off(a_row[mt], a_hi));
        #pragma unroll
        for (int bt = 0; bt < 2; bt++)
            ldsm_x4(b[0][bt][0], b[0][bt][1], b[0][bt][2], b[0][bt][3],
                    bb + sw_off(b_row[bt], a_hi));

        #pragma unroll
        for (int ks = 0; ks < 4; ks++) {
            const int cur = ks & 1, nxt = cur ^ 1;
            if (ks < 3) {                          // prefetch ks+1
                #pragma unroll
                for (int mt = 0; mt < 4; mt++)
                    ldsm_x4(a[nxt][mt][0], a[nxt][mt][1], a[nxt][mt][2], a[nxt][mt][3],
                            ab + sw_off(a_row[mt], (ks + 1) * 2 + a_hi));
                #pragma unroll
                for (int bt = 0; bt < 2; bt++)
                    ldsm_x4(b[nxt][bt][0], b[nxt][bt][1], b[nxt][bt][2], b[nxt][bt][3],
                            bb + sw_off(b_row[bt], (ks + 1) * 2 + a_hi));
            }
            #pragma unroll
            for (int mt = 0; mt < 4; mt++) {
                #pragma unroll
                for (int nt = 0; nt < 4; nt++) {
                    const int bt = nt >> 1, sub = nt & 1;
                    mma_16816(c[mt][nt][0], c[mt][nt][1], c[mt][nt][2], c[mt][nt][3],
                              a[cur][mt][0], a[cur][mt][1], a[cur][mt][2], a[cur][mt][3],
                              b[cur][bt][sub], b[cur][bt][2 + sub]);
                }
            }
        }
    }

    // ---- epilogue: cos -> feat (+ margin at label) ----
    const float inv_pi     = 1.0f / CUDART_PI_F;
    const float inv_1plamb = 1.0f / 1001.0f;

    #pragma unroll
    for (int mt = 0; mt < 4; mt++) {
        const int r0 = bm + wm * 64 + mt * 16 + (lane >> 2);
        const int r1 = r0 + 8;
        const float xl0 = g_xlen[r0], xl1 = g_xlen[r1];
        const int  lab0 = Y[r0],      lab1 = Y[r1];
        #pragma unroll
        for (int nt = 0; nt < 4; nt++) {
            const int col = bn + wn * 32 + nt * 8 + (lane & 3) * 2;
            if (col >= C) continue;          // col even, C even -> col+1 valid
            #pragma unroll
            for (int half = 0; half < 2; half++) {
                const int   rr  = half ? r1 : r0;
                const float xl  = half ? xl1 : xl0;
                const int   lab = half ? lab1 : lab0;
                float v0 = c[mt][nt][half * 2 + 0];
                float v1 = c[mt][nt][half * 2 + 1];
                v0 = fminf(fmaxf(v0, -1.0f), 1.0f);
                v1 = fminf(fmaxf(v1, -1.0f), 1.0f);
                float f0 = v0 * xl, f1 = v1 * xl;
                if (col == lab || col + 1 == lab) {
                    const bool second = (col + 1 == lab);
                    float cv = second ? v1 : v0;
                    float c2   = cv * cv;
                    float cosm = 8.0f * c2 * c2 - 8.0f * c2 + 1.0f;
                    float kf   = floorf(4.0f * acosf(cv) * inv_pi);
                    float sign = 1.0f - 2.0f * fmodf(kf, 2.0f);
                    float phi  = sign * cosm - 2.0f * kf;
                    float fm   = second ? f1 : f0;
                    fm += (phi * xl - fm) * inv_1plamb;
                    if (second) f1 = fm; else f0 = fm;
                }
                *(float2*)(out + (size_t)rr * C + col) = make_float2(f0, f1);
            }
        }
    }
}

// ---------------------------------------------------------------------------
// Launch
// ---------------------------------------------------------------------------
extern "C" void kernel_launch(void* const* d_in, const int* in_sizes, int n_in,
                              void* d_out, int out_size)
{
    const float* x = (const float*)d_in[0];
    const float* w = (const float*)d_in[1];
    const int*   y = (const int*)d_in[2];
    float* out     = (float*)d_out;

    const int B = in_sizes[2];            // 512
    const int D = in_sizes[0] / B;        // 256
    const int C = in_sizes[1] / D;        // 100000
    (void)D;

    static bool attr_set = false;
    if (!attr_set) {
        cudaFuncSetAttribute(angle_mma_kernel,
                             cudaFuncAttributeMaxDynamicSharedMemorySize, SMEM_TOTAL);
        attr_set = true;
    }

    {
        int wpb = 8;
        int rows = C + B;
        prep_kernel<<<(rows + wpb - 1) / wpb, wpb * 32>>>(w, x, C, B);
    }

    // grid.x = m tiles (fastest -> 4 CTAs share each W n-stripe in L2)
    dim3 grid(B / BM, (C + BN - 1) / BN);
    angle_mma_kernel<<<grid, 256, SMEM_TOTAL>>>(y, out, C);
}